// round 1
// baseline (speedup 1.0000x reference)
#include <cuda_runtime.h>
#include <cuda_bf16.h>

// PatchFFTLoss: mean over all 8x8-patch FFT bins of
//   (g(Re Fi)-g(Re Ft))^2 + (g(Im Fi)-g(Im Ft))^2,  g(x)=sign(x)*log1p(|x|)
// fftshift dropped (permutation under a full mean). FFT output order free
// (same network for input & target), so DIF bit-reversed order is used as-is.

#define NPATCH   (16 * 3 * 64 * 64)        // 196608 patches
#define NTHREADS (NPATCH * 8)              // one thread per patch row
#define BLOCK    256
#define NBLOCKS  (NTHREADS / BLOCK)        // 6144
#define INV_N    (1.0f / 12582912.0f)      // mean denominator: 16*3*64*64*64

__device__ float g_partials[NBLOCKS];

__device__ __forceinline__ float sgnlog1p(float x) {
    return copysignf(__logf(1.0f + fabsf(x)), x);
}

// Per-thread: row FFT (8 real -> 8 complex) + cross-lane 8-pt column FFT
// over the 8 threads of the patch group, then signed-log1p of all 16 floats.
__device__ __forceinline__ void fft_feats(const float x[8],
                                          bool up1, float wr1, float wi1,
                                          bool up2, float wr2, float wi2,
                                          bool up3,
                                          float g[16])
{
    const float C = 0.70710678118654752f;

    // ---- row FFT of real input (any consistent output order is fine) ----
    float a04p = x[0] + x[4], a04m = x[0] - x[4];
    float a26p = x[2] + x[6], a26m = x[2] - x[6];
    float E0 = a04p + a26p,  E2 = a04p - a26p;
    float b15p = x[1] + x[5], b15m = x[1] - x[5];
    float b37p = x[3] + x[7], b37m = x[3] - x[7];
    float O0 = b15p + b37p,  O2 = b15p - b37p;
    float t1 =  C * (b15m - b37m);
    float t2 = -C * (b15m + b37m);

    float zr[8], zi[8];
    zr[0] = E0 + O0;    zi[0] = 0.0f;
    zr[1] = a04m + t1;  zi[1] = -a26m + t2;
    zr[2] = E2;         zi[2] = -O2;
    zr[3] = a04m - t1;  zi[3] =  a26m + t2;
    zr[4] = E0 - O0;    zi[4] = 0.0f;
    zr[5] = a04m - t1;  zi[5] = -a26m - t2;
    zr[6] = E2;         zi[6] =  O2;
    zr[7] = a04m + t1;  zi[7] =  a26m - t2;

    // ---- column FFT across the 8 lanes of this patch group (DIF) ----
    // stage 1: distance 4, twiddle W8^(t&3) on upper lanes
    #pragma unroll
    for (int v = 0; v < 8; v++) {
        float pr = __shfl_xor_sync(0xffffffffu, zr[v], 4);
        float pi = __shfl_xor_sync(0xffffffffu, zi[v], 4);
        float sr = zr[v] + pr, si = zi[v] + pi;
        float dr = pr - zr[v], di = pi - zi[v];
        float tr = dr * wr1 - di * wi1;
        float ti = dr * wi1 + di * wr1;
        zr[v] = up1 ? tr : sr;
        zi[v] = up1 ? ti : si;
    }
    // stage 2: distance 2, twiddle W4^(t&1) on upper lanes
    #pragma unroll
    for (int v = 0; v < 8; v++) {
        float pr = __shfl_xor_sync(0xffffffffu, zr[v], 2);
        float pi = __shfl_xor_sync(0xffffffffu, zi[v], 2);
        float sr = zr[v] + pr, si = zi[v] + pi;
        float dr = pr - zr[v], di = pi - zi[v];
        float tr = dr * wr2 - di * wi2;
        float ti = dr * wi2 + di * wr2;
        zr[v] = up2 ? tr : sr;
        zi[v] = up2 ? ti : si;
    }
    // stage 3: distance 1, no twiddle
    #pragma unroll
    for (int v = 0; v < 8; v++) {
        float pr = __shfl_xor_sync(0xffffffffu, zr[v], 1);
        float pi = __shfl_xor_sync(0xffffffffu, zi[v], 1);
        zr[v] = up3 ? (pr - zr[v]) : (zr[v] + pr);
        zi[v] = up3 ? (pi - zi[v]) : (zi[v] + pi);
    }

    // ---- signed log1p features ----
    #pragma unroll
    for (int v = 0; v < 8; v++) {
        g[2 * v]     = sgnlog1p(zr[v]);
        g[2 * v + 1] = sgnlog1p(zi[v]);
    }
}

__global__ void __launch_bounds__(BLOCK)
patch_fft_loss_kernel(const float* __restrict__ inp, const float* __restrict__ tgt)
{
    const int gid = blockIdx.x * BLOCK + threadIdx.x;
    const int t  = gid & 7;          // row within patch == lane within 8-group
    const int p  = gid >> 3;         // patch index
    const int pw = p & 63;
    const int ph = (p >> 6) & 63;
    const int bc = p >> 12;          // combined (batch, channel), 0..47

    const size_t base = ((size_t)(bc * 512 + ph * 8 + t)) * 512 + (size_t)pw * 8;

    // per-lane butterfly constants
    const float C = 0.70710678118654752f;
    const bool up1 = (t & 4) != 0;
    const bool up2 = (t & 2) != 0;
    const bool up3 = (t & 1) != 0;
    const int  jj  = t & 3;
    const float wr1 = (jj == 0) ? 1.0f : (jj == 1) ? C : (jj == 2) ? 0.0f : -C;
    const float wi1 = (jj == 0) ? 0.0f : (jj == 2) ? -1.0f : -C;
    const float wr2 = (t & 1) ? 0.0f : 1.0f;
    const float wi2 = (t & 1) ? -1.0f : 0.0f;

    float x[8];
    float gi[16], gt[16];

    // input tensor (ortho norm 1/8 pre-applied: FFT is linear)
    {
        float4 a = *(const float4*)(inp + base);
        float4 b = *(const float4*)(inp + base + 4);
        x[0] = a.x * 0.125f; x[1] = a.y * 0.125f; x[2] = a.z * 0.125f; x[3] = a.w * 0.125f;
        x[4] = b.x * 0.125f; x[5] = b.y * 0.125f; x[6] = b.z * 0.125f; x[7] = b.w * 0.125f;
        fft_feats(x, up1, wr1, wi1, up2, wr2, wi2, up3, gi);
    }
    // target tensor
    {
        float4 a = *(const float4*)(tgt + base);
        float4 b = *(const float4*)(tgt + base + 4);
        x[0] = a.x * 0.125f; x[1] = a.y * 0.125f; x[2] = a.z * 0.125f; x[3] = a.w * 0.125f;
        x[4] = b.x * 0.125f; x[5] = b.y * 0.125f; x[6] = b.z * 0.125f; x[7] = b.w * 0.125f;
        fft_feats(x, up1, wr1, wi1, up2, wr2, wi2, up3, gt);
    }

    float acc = 0.0f;
    #pragma unroll
    for (int k = 0; k < 16; k++) {
        float d = gi[k] - gt[k];
        acc = fmaf(d, d, acc);
    }

    // deterministic block reduction
    __shared__ float sm[BLOCK];
    sm[threadIdx.x] = acc;
    __syncthreads();
    #pragma unroll
    for (int o = BLOCK / 2; o > 0; o >>= 1) {
        if (threadIdx.x < o) sm[threadIdx.x] += sm[threadIdx.x + o];
        __syncthreads();
    }
    if (threadIdx.x == 0) g_partials[blockIdx.x] = sm[0];
}

__global__ void __launch_bounds__(1024)
reduce_kernel(float* __restrict__ out)
{
    __shared__ float sm[1024];
    float a = 0.0f;
    for (int i = threadIdx.x; i < NBLOCKS; i += 1024) a += g_partials[i];
    sm[threadIdx.x] = a;
    __syncthreads();
    #pragma unroll
    for (int o = 512; o > 0; o >>= 1) {
        if (threadIdx.x < o) sm[threadIdx.x] += sm[threadIdx.x + o];
        __syncthreads();
    }
    if (threadIdx.x == 0) out[0] = sm[0] * INV_N;
}

extern "C" void kernel_launch(void* const* d_in, const int* in_sizes, int n_in,
                              void* d_out, int out_size)
{
    const float* inp = (const float*)d_in[0];
    const float* tgt = (const float*)d_in[1];
    patch_fft_loss_kernel<<<NBLOCKS, BLOCK>>>(inp, tgt);
    reduce_kernel<<<1, 1024>>>((float*)d_out);
}

// round 2
// speedup vs baseline: 1.3026x; 1.3026x over previous
#include <cuda_runtime.h>
#include <cuda_bf16.h>

// PatchFFTLoss, round 2:
//  - z = (input + i*target)/16 : ONE complex 8x8 FFT per patch instead of two
//    real ones; Hermitian separation recovers both spectra (1/2 folded into scale).
//  - conjugate-symmetry: bins (u,v) and (-u,-v) contribute equal loss, so only
//    slots v=0..4 are evaluated, with weights {lane-dep,2,2,2,lane-dep}.
//  - logs in base 2; ln2^2 folded into the final mean scale.
//  - fftshift dropped (permutation under a full mean); FFT output order free.
//  - single fused kernel: last-block-done global reduction (self-resetting
//    counter, fixed-order sums -> bit-deterministic, graph-capturable).

#define NPATCH   (16 * 3 * 64 * 64)       // 196608
#define NTHREADS (NPATCH * 8)
#define BLOCK    256
#define NBLOCKS  (NTHREADS / BLOCK)       // 6144
#define LN2      0.69314718055994530942f
#define FINAL_SCALE ((LN2 * LN2) / 12582912.0f)   // ln2^2 / (NPATCH*64)

__device__ float g_partials[NBLOCKS];
__device__ unsigned int g_count = 0;

__device__ __forceinline__ float sgnlg2(float x) {
    // sign(x) * log2(1+|x|); log1p's ln2 factor applied once in FINAL_SCALE
    return copysignf(__log2f(1.0f + fabsf(x)), x);
}

__global__ void __launch_bounds__(BLOCK)
patch_fft_loss_kernel(const float* __restrict__ inp,
                      const float* __restrict__ tgt,
                      float* __restrict__ out)
{
    const int gid = blockIdx.x * BLOCK + threadIdx.x;
    const int t  = gid & 7;          // patch row == lane within 8-group
    const int p  = gid >> 3;
    const int pw = p & 63;
    const int ph = (p >> 6) & 63;
    const int bc = p >> 12;          // (batch,channel) combined
    const size_t base = ((size_t)(bc * 512 + ph * 8 + t)) * 512 + (size_t)pw * 8;

    // ---- load packed complex row: z = (inp + i*tgt) / 16 ----
    float zr[8], zi[8];
    {
        float4 a = *(const float4*)(inp + base);
        float4 b = *(const float4*)(inp + base + 4);
        zr[0]=a.x*0.0625f; zr[1]=a.y*0.0625f; zr[2]=a.z*0.0625f; zr[3]=a.w*0.0625f;
        zr[4]=b.x*0.0625f; zr[5]=b.y*0.0625f; zr[6]=b.z*0.0625f; zr[7]=b.w*0.0625f;
        float4 c = *(const float4*)(tgt + base);
        float4 d = *(const float4*)(tgt + base + 4);
        zi[0]=c.x*0.0625f; zi[1]=c.y*0.0625f; zi[2]=c.z*0.0625f; zi[3]=c.w*0.0625f;
        zi[4]=d.x*0.0625f; zi[5]=d.y*0.0625f; zi[6]=d.z*0.0625f; zi[7]=d.w*0.0625f;
    }

    const float C = 0.70710678118654752440f;

    // ---- row FFT: 8-pt complex DIF, relabeled to natural-order bins ----
    float A0r=zr[0]+zr[4], A0i=zi[0]+zi[4];
    float A1r=zr[1]+zr[5], A1i=zi[1]+zi[5];
    float A2r=zr[2]+zr[6], A2i=zi[2]+zi[6];
    float A3r=zr[3]+zr[7], A3i=zi[3]+zi[7];
    float B0r=zr[0]-zr[4], B0i=zi[0]-zi[4];
    float d1r=zr[1]-zr[5], d1i=zi[1]-zi[5];
    float B1r=C*(d1r+d1i), B1i=C*(d1i-d1r);          // *W8^1
    float B2r=zi[2]-zi[6], B2i=zr[6]-zr[2];          // *W8^2 = -i
    float d3r=zr[3]-zr[7], d3i=zi[3]-zi[7];
    float B3r=C*(d3i-d3r), B3i=-C*(d3r+d3i);         // *W8^3

    float A20r=A0r+A2r, A20i=A0i+A2i;
    float A22r=A0r-A2r, A22i=A0i-A2i;
    float A21r=A1r+A3r, A21i=A1i+A3i;
    float A23r=A1i-A3i, A23i=A3r-A1r;                // (A1-A3)*(-i)
    float B20r=B0r+B2r, B20i=B0i+B2i;
    float B22r=B0r-B2r, B22i=B0i-B2i;
    float B21r=B1r+B3r, B21i=B1i+B3i;
    float B23r=B1i-B3i, B23i=B3r-B1r;                // (B1-B3)*(-i)

    float Xr[8], Xi[8];
    Xr[0]=A20r+A21r; Xi[0]=A20i+A21i;
    Xr[4]=A20r-A21r; Xi[4]=A20i-A21i;
    Xr[2]=A22r+A23r; Xi[2]=A22i+A23i;
    Xr[6]=A22r-A23r; Xi[6]=A22i-A23i;
    Xr[1]=B20r+B21r; Xi[1]=B20i+B21i;
    Xr[5]=B20r-B21r; Xi[5]=B20i-B21i;
    Xr[3]=B22r+B23r; Xi[3]=B22i+B23i;
    Xr[7]=B22r-B23r; Xi[7]=B22i-B23i;

    // ---- column FFT across the 8 lanes (DIF, lane t ends with bin rev3(t)) ----
    const float s1 = (t & 4) ? -1.0f : 1.0f;
    const float s2 = (t & 2) ? -1.0f : 1.0f;
    const float s3 = (t & 1) ? -1.0f : 1.0f;
    const int j = t & 3;
    float w1r, w1i;
    if (t & 4) {
        w1r = (j==0)?1.0f:(j==1)?C:(j==2)?0.0f:-C;
        w1i = (j==0)?0.0f:((j==2)?-1.0f:-C);
    } else { w1r = 1.0f; w1i = 0.0f; }
    const bool u2 = ((t & 2) != 0) && ((t & 1) != 0);
    const float w2r = u2 ? 0.0f : 1.0f;
    const float w2i = u2 ? -1.0f : 0.0f;

    #pragma unroll
    for (int v = 0; v < 8; v++) {
        float pr = __shfl_xor_sync(0xffffffffu, Xr[v], 4);
        float pi = __shfl_xor_sync(0xffffffffu, Xi[v], 4);
        float dr = fmaf(s1, Xr[v], pr);
        float di = fmaf(s1, Xi[v], pi);
        Xr[v] = fmaf(dr, w1r, -di * w1i);
        Xi[v] = fmaf(dr, w1i,  di * w1r);
        pr = __shfl_xor_sync(0xffffffffu, Xr[v], 2);
        pi = __shfl_xor_sync(0xffffffffu, Xi[v], 2);
        dr = fmaf(s2, Xr[v], pr);
        di = fmaf(s2, Xi[v], pi);
        Xr[v] = fmaf(dr, w2r, -di * w2i);
        Xi[v] = fmaf(dr, w2i,  di * w2r);
        pr = __shfl_xor_sync(0xffffffffu, Xr[v], 1);
        pi = __shfl_xor_sync(0xffffffffu, Xi[v], 1);
        Xr[v] = fmaf(s3, Xr[v], pr);
        Xi[v] = fmaf(s3, Xi[v], pi);
    }

    // ---- Hermitian separation + loss on canonical half ----
    // lane t holds bin u = rev3(t); conj partner bin (-u) lives at lane sigma(t)
    const int sig = (0x45672310u >> (t * 4)) & 7;     // sigma = [0,1,3,2,7,6,5,4]
    // weight for slots v=0,4: u in {0,4} -> 1 ; u in {1,2,3} -> 2 ; u in {5,6,7} -> 0
    const float w04 = (t < 2) ? 1.0f : ((t & 1) ? 0.0f : 2.0f);

    float acc2 = 0.0f, accA = 0.0f;
    #pragma unroll
    for (int v = 0; v <= 4; v++) {
        const int nv = (8 - v) & 7;
        float Znr = __shfl_sync(0xffffffffu, Xr[nv], sig, 8);
        float Zni = __shfl_sync(0xffffffffu, Xi[nv], sig, 8);
        // Fi = Z + conj(Zn), Ft = -i*(Z - conj(Zn))   (1/2 folded into load scale)
        float fir = Xr[v] + Znr;
        float fii = Xi[v] - Zni;
        float ftr = Xi[v] + Zni;
        float fti = Znr - Xr[v];
        float d1 = sgnlg2(fir) - sgnlg2(ftr);
        float d2 = sgnlg2(fii) - sgnlg2(fti);
        float l = fmaf(d1, d1, d2 * d2);
        if (v == 0 || v == 4) accA += l; else acc2 += l;
    }
    float acc = fmaf(2.0f, acc2, w04 * accA);

    // ---- deterministic reduction: warp -> block -> last-block-done global ----
    #pragma unroll
    for (int o = 16; o > 0; o >>= 1)
        acc += __shfl_xor_sync(0xffffffffu, acc, o);

    __shared__ float smw[BLOCK / 32];
    __shared__ bool isLast;
    if ((threadIdx.x & 31) == 0) smw[threadIdx.x >> 5] = acc;
    __syncthreads();
    if (threadIdx.x == 0) {
        float s = 0.0f;
        #pragma unroll
        for (int i = 0; i < BLOCK / 32; i++) s += smw[i];
        g_partials[blockIdx.x] = s;
        __threadfence();
        unsigned old = atomicInc(&g_count, NBLOCKS - 1);  // wraps to 0 on last
        isLast = (old == NBLOCKS - 1);
    }
    __syncthreads();

    if (isLast) {
        float a = 0.0f;
        for (int i = threadIdx.x; i < NBLOCKS; i += BLOCK)
            a += __ldcg(&g_partials[i]);
        #pragma unroll
        for (int o = 16; o > 0; o >>= 1)
            a += __shfl_xor_sync(0xffffffffu, a, o);
        if ((threadIdx.x & 31) == 0) smw[threadIdx.x >> 5] = a;
        __syncthreads();
        if (threadIdx.x == 0) {
            float s = 0.0f;
            #pragma unroll
            for (int i = 0; i < BLOCK / 32; i++) s += smw[i];
            out[0] = s * FINAL_SCALE;
        }
    }
}

extern "C" void kernel_launch(void* const* d_in, const int* in_sizes, int n_in,
                              void* d_out, int out_size)
{
    const float* inp = (const float*)d_in[0];
    const float* tgt = (const float*)d_in[1];
    patch_fft_loss_kernel<<<NBLOCKS, BLOCK>>>(inp, tgt, (float*)d_out);
}

// round 3
// speedup vs baseline: 1.9098x; 1.4662x over previous
#include <cuda_runtime.h>
#include <cuda_bf16.h>

// PatchFFTLoss round 3: 2 threads per patch, 4 rows per thread.
//  - z = (input + i*target)/16, one complex 8x8 FFT, Hermitian separation.
//  - column FFT stages (dist 4, dist 2) in-register; only dist-1 stage and
//    Hermitian partner fetch cross lanes (xor 1)  -> 188 shuffles/patch vs 464.
//  - conjugate symmetry: only v=0..4 evaluated with weights.
//  - fused last-block-done reduction, bit-deterministic, graph-capturable.

#define NPATCH   (16 * 3 * 64 * 64)       // 196608
#define NTHREADS (NPATCH * 2)             // 393216
#define BLOCK    256
#define NBLOCKS  (NTHREADS / BLOCK)       // 1536
#define LN2      0.69314718055994530942f
#define FINAL_SCALE ((LN2 * LN2) / 12582912.0f)

__device__ float g_partials[NBLOCKS];
__device__ unsigned int g_count = 0;

__device__ __forceinline__ float sgnlg2(float x) {
    return copysignf(__log2f(1.0f + fabsf(x)), x);
}

// loss cell: Z at (u,v), Zn = Z at (-u, -v); recovers Fi, Ft and accumulates
__device__ __forceinline__ float cell(float Zr_, float Zi_, float Znr, float Zni) {
    float fir = Zr_ + Znr;
    float fii = Zi_ - Zni;
    float ftr = Zi_ + Zni;
    float fti = Znr - Zr_;
    float d1 = sgnlg2(fir) - sgnlg2(ftr);
    float d2 = sgnlg2(fii) - sgnlg2(fti);
    return fmaf(d1, d1, d2 * d2);
}

// 8-pt complex FFT, natural-order output bins (validated in round 2)
__device__ __forceinline__ void rowfft(const float zr[8], const float zi[8],
                                       float Xr[8], float Xi[8]) {
    const float C = 0.70710678118654752440f;
    float A0r=zr[0]+zr[4], A0i=zi[0]+zi[4];
    float A1r=zr[1]+zr[5], A1i=zi[1]+zi[5];
    float A2r=zr[2]+zr[6], A2i=zi[2]+zi[6];
    float A3r=zr[3]+zr[7], A3i=zi[3]+zi[7];
    float B0r=zr[0]-zr[4], B0i=zi[0]-zi[4];
    float d1r=zr[1]-zr[5], d1i=zi[1]-zi[5];
    float B1r=C*(d1r+d1i), B1i=C*(d1i-d1r);
    float B2r=zi[2]-zi[6], B2i=zr[6]-zr[2];
    float d3r=zr[3]-zr[7], d3i=zi[3]-zi[7];
    float B3r=C*(d3i-d3r), B3i=-C*(d3r+d3i);

    float A20r=A0r+A2r, A20i=A0i+A2i;
    float A22r=A0r-A2r, A22i=A0i-A2i;
    float A21r=A1r+A3r, A21i=A1i+A3i;
    float A23r=A1i-A3i, A23i=A3r-A1r;
    float B20r=B0r+B2r, B20i=B0i+B2i;
    float B22r=B0r-B2r, B22i=B0i-B2i;
    float B21r=B1r+B3r, B21i=B1i+B3i;
    float B23r=B1i-B3i, B23i=B3r-B1r;

    Xr[0]=A20r+A21r; Xi[0]=A20i+A21i;
    Xr[4]=A20r-A21r; Xi[4]=A20i-A21i;
    Xr[2]=A22r+A23r; Xi[2]=A22i+A23i;
    Xr[6]=A22r-A23r; Xi[6]=A22i-A23i;
    Xr[1]=B20r+B21r; Xi[1]=B20i+B21i;
    Xr[5]=B20r-B21r; Xi[5]=B20i-B21i;
    Xr[3]=B22r+B23r; Xi[3]=B22i+B23i;
    Xr[7]=B22r-B23r; Xi[7]=B22i-B23i;
}

__global__ void __launch_bounds__(BLOCK, 2)
patch_fft_loss_kernel(const float* __restrict__ inp,
                      const float* __restrict__ tgt,
                      float* __restrict__ out)
{
    const int gid = blockIdx.x * BLOCK + threadIdx.x;
    const int t  = gid & 1;           // lane within patch pair
    const int p  = gid >> 1;
    const int pw = p & 63;
    const int ph = (p >> 6) & 63;
    const int bc = p >> 12;

    const float C = 0.70710678118654752440f;

    // slot s holds patch row (t + 2s); Z = row FFT of (inp + i*tgt)/16
    float Zr[4][8], Zi[4][8];
    #pragma unroll
    for (int s = 0; s < 4; s++) {
        const size_t base = ((size_t)(bc * 512 + ph * 8 + t + 2 * s)) * 512
                          + (size_t)pw * 8;
        float zr[8], zi[8];
        float4 a = *(const float4*)(inp + base);
        float4 b = *(const float4*)(inp + base + 4);
        zr[0]=a.x*0.0625f; zr[1]=a.y*0.0625f; zr[2]=a.z*0.0625f; zr[3]=a.w*0.0625f;
        zr[4]=b.x*0.0625f; zr[5]=b.y*0.0625f; zr[6]=b.z*0.0625f; zr[7]=b.w*0.0625f;
        float4 c = *(const float4*)(tgt + base);
        float4 d = *(const float4*)(tgt + base + 4);
        zi[0]=c.x*0.0625f; zi[1]=c.y*0.0625f; zi[2]=c.z*0.0625f; zi[3]=c.w*0.0625f;
        zi[4]=d.x*0.0625f; zi[5]=d.y*0.0625f; zi[6]=d.z*0.0625f; zi[7]=d.w*0.0625f;
        rowfft(zr, zi, Zr[s], Zi[s]);
    }

    // column FFT over rows r = t + 2s; stages 1,2 in-register, stage 3 xor-1.
    // lane-dependent twiddles: wa = W8^t, wb = W8^(t+2), wc = W4^t
    const float war = t ? C : 1.0f,  wai = t ? -C : 0.0f;
    const float wbr = t ? -C : 0.0f, wbi = t ? -C : -1.0f;
    const float wcr = t ? 0.0f : 1.0f, wci = t ? -1.0f : 0.0f;
    const float sgn = t ? -1.0f : 1.0f;

    #pragma unroll
    for (int v = 0; v < 8; v++) {
        // stage 1 (rows r', r'+4): A[q] = f+f4 ; B[q] = (f-f4)*W8^{r'}
        float A0r = Zr[0][v] + Zr[2][v], A0i = Zi[0][v] + Zi[2][v];
        float A1r = Zr[1][v] + Zr[3][v], A1i = Zi[1][v] + Zi[3][v];
        float e0r = Zr[0][v] - Zr[2][v], e0i = Zi[0][v] - Zi[2][v];
        float e1r = Zr[1][v] - Zr[3][v], e1i = Zi[1][v] - Zi[3][v];
        float B0r = e0r * war - e0i * wai, B0i = e0r * wai + e0i * war;
        float B1r = e1r * wbr - e1i * wbi, B1i = e1r * wbi + e1i * wbr;
        // stage 2: E = +; O = (-)*W4^t
        float EAr = A0r + A1r, EAi = A0i + A1i;
        float oar = A0r - A1r, oai = A0i - A1i;
        float OAr = oar * wcr - oai * wci, OAi = oar * wci + oai * wcr;
        float EBr = B0r + B1r, EBi = B0i + B1i;
        float obr = B0r - B1r, obi = B0i - B1i;
        float OBr = obr * wcr - obi * wci, OBi = obr * wci + obi * wcr;
        // stage 3 (xor 1): lane0 -> own+peer, lane1 -> peer-own
        // chains stored: slot0=EA (u=4t), slot1=OA (u=2+4t),
        //                slot2=EB (u=1+4t), slot3=OB (u=3+4t)
        Zr[0][v] = fmaf(sgn, EAr, __shfl_xor_sync(0xffffffffu, EAr, 1));
        Zi[0][v] = fmaf(sgn, EAi, __shfl_xor_sync(0xffffffffu, EAi, 1));
        Zr[1][v] = fmaf(sgn, OAr, __shfl_xor_sync(0xffffffffu, OAr, 1));
        Zi[1][v] = fmaf(sgn, OAi, __shfl_xor_sync(0xffffffffu, OAi, 1));
        Zr[2][v] = fmaf(sgn, EBr, __shfl_xor_sync(0xffffffffu, EBr, 1));
        Zi[2][v] = fmaf(sgn, EBi, __shfl_xor_sync(0xffffffffu, EBi, 1));
        Zr[3][v] = fmaf(sgn, OBr, __shfl_xor_sync(0xffffffffu, OBr, 1));
        Zi[3][v] = fmaf(sgn, OBi, __shfl_xor_sync(0xffffffffu, OBi, 1));
    }

    // Hermitian separation + loss over canonical half (v = 0..4).
    // Partners: EA <-> own EA (v-flip); OA <-> peer OA; EB <-> peer OB;
    //           OB <-> peer EB. All peer fetches are xor-1 shuffles.
    const float wz = t ? 0.0f : 1.0f;    // v in {0,4}: lane1's OA/EB/OB weight 0
    float acc1 = 0.0f, acc2 = 0.0f;
    #pragma unroll
    for (int v = 0; v <= 4; v++) {
        const int vp = (8 - v) & 7;
        float lEA = cell(Zr[0][v], Zi[0][v], Zr[0][vp], Zi[0][vp]);
        float nr, ni;
        nr = __shfl_xor_sync(0xffffffffu, Zr[1][vp], 1);
        ni = __shfl_xor_sync(0xffffffffu, Zi[1][vp], 1);
        float lOA = cell(Zr[1][v], Zi[1][v], nr, ni);
        nr = __shfl_xor_sync(0xffffffffu, Zr[3][vp], 1);
        ni = __shfl_xor_sync(0xffffffffu, Zi[3][vp], 1);
        float lEB = cell(Zr[2][v], Zi[2][v], nr, ni);
        nr = __shfl_xor_sync(0xffffffffu, Zr[2][vp], 1);
        ni = __shfl_xor_sync(0xffffffffu, Zi[2][vp], 1);
        float lOB = cell(Zr[3][v], Zi[3][v], nr, ni);
        float l3 = lOA + lEB + lOB;
        if (v == 0 || v == 4) {
            acc1 += lEA;                 // self-conj u in {0,4}: weight 1
            acc2 = fmaf(wz, l3, acc2);   // u in {1,2,3}: w2 ; u in {5,6,7}: 0
        } else {
            acc2 += lEA + l3;            // weight 2 (covers v in {5,6,7})
        }
    }
    float acc = fmaf(2.0f, acc2, acc1);

    // deterministic reduction: warp -> block -> last-block-done global
    #pragma unroll
    for (int o = 16; o > 0; o >>= 1)
        acc += __shfl_xor_sync(0xffffffffu, acc, o);

    __shared__ float smw[BLOCK / 32];
    __shared__ bool isLast;
    if ((threadIdx.x & 31) == 0) smw[threadIdx.x >> 5] = acc;
    __syncthreads();
    if (threadIdx.x == 0) {
        float s = 0.0f;
        #pragma unroll
        for (int i = 0; i < BLOCK / 32; i++) s += smw[i];
        g_partials[blockIdx.x] = s;
        __threadfence();
        unsigned old = atomicInc(&g_count, NBLOCKS - 1);  // wraps to 0 on last
        isLast = (old == NBLOCKS - 1);
    }
    __syncthreads();

    if (isLast) {
        float a = 0.0f;
        #pragma unroll
        for (int i = 0; i < NBLOCKS / BLOCK; i++)
            a += __ldcg(&g_partials[threadIdx.x + i * BLOCK]);
        #pragma unroll
        for (int o = 16; o > 0; o >>= 1)
            a += __shfl_xor_sync(0xffffffffu, a, o);
        if ((threadIdx.x & 31) == 0) smw[threadIdx.x >> 5] = a;
        __syncthreads();
        if (threadIdx.x == 0) {
            float s = 0.0f;
            #pragma unroll
            for (int i = 0; i < BLOCK / 32; i++) s += smw[i];
            out[0] = s * FINAL_SCALE;
        }
    }
}

extern "C" void kernel_launch(void* const* d_in, const int* in_sizes, int n_in,
                              void* d_out, int out_size)
{
    const float* inp = (const float*)d_in[0];
    const float* tgt = (const float*)d_in[1];
    patch_fft_loss_kernel<<<NBLOCKS, BLOCK>>>(inp, tgt, (float*)d_out);
}